// round 4
// baseline (speedup 1.0000x reference)
#include <cuda_runtime.h>

#define HH 1024
#define WW 1024
#define HW (HH*WW)
#define NT 256
#define NB4 (HW/4/NT)   // 1024 blocks for 4px/thread flat kernels

// ---------------- device scratch ----------------
__device__ __align__(16) float g_rhoc[HW];
__device__ __align__(16) float g_gi0[HW];
__device__ __align__(16) float g_gi1[HW];
__device__ __align__(16) float g_u[2][2*HW];
__device__ __align__(16) float g_p[2][4*HW];
__device__ float g_partial[NB4];
__device__ unsigned int g_count;
__device__ float g_S;

__device__ __forceinline__ float4 ldg4(const float* p) { return *(const float4*)p; }

// ---------------- K0: rho_c, grad_im; zero P_0 ----------------
__global__ void __launch_bounds__(NT) k_init(const float* __restrict__ x, const float* __restrict__ gw) {
    int t4 = blockIdx.x * NT + threadIdx.x;
    int pix = t4 * 4;
    int y = pix >> 10, x0 = pix & (WW - 1);
    const float* __restrict__ x1 = x + HW;

    float w0[9], w1[9];
    #pragma unroll
    for (int i = 0; i < 9; i++) { w0[i] = __ldg(&gw[i]); w1[i] = __ldg(&gw[9 + i]); }

    float t[3][6];
    #pragma unroll
    for (int r = 0; r < 3; r++) {
        int yy = y - 1 + r; bool vy = (yy >= 0 && yy < HH);
        const float* row = x1 + yy * WW;
        float l = (vy && x0 > 0) ? row[x0 - 1] : 0.f;
        float4 b = vy ? ldg4(row + x0) : make_float4(0.f,0.f,0.f,0.f);
        float rg = (vy && x0 < WW - 4) ? row[x0 + 4] : 0.f;
        t[r][0]=l; t[r][1]=b.x; t[r][2]=b.y; t[r][3]=b.z; t[r][4]=b.w; t[r][5]=rg;
    }

    float4 xc0 = ldg4(x + pix);
    float4 xc1 = ldg4(x1 + pix);
    *(float4*)(g_rhoc + pix) = make_float4(xc1.x-xc0.x, xc1.y-xc0.y, xc1.z-xc0.z, xc1.w-xc0.w);

    float4 A, B;
    float* Ap = &A.x; float* Bp = &B.x;
    #pragma unroll
    for (int i = 0; i < 4; i++) {
        float a = 0.f, b = 0.f;
        #pragma unroll
        for (int r = 0; r < 3; r++)
            #pragma unroll
            for (int c = 0; c < 3; c++) { float v = t[r][i + c]; a += v * w0[r*3+c]; b += v * w1[r*3+c]; }
        Ap[i] = a; Bp[i] = b;
    }
    *(float4*)(g_gi0 + pix) = A;
    *(float4*)(g_gi1 + pix) = B;

    float4 z = make_float4(0.f,0.f,0.f,0.f);
    *(float4*)(g_p[0] + pix) = z;
    *(float4*)(g_p[0] + HW + pix) = z;
    *(float4*)(g_p[0] + 2*HW + pix) = z;
    *(float4*)(g_p[0] + 3*HW + pix) = z;
    if (pix == 0) g_count = 0u;
}

// ---------------- K_first: t=0 (u=0, p=0) ----------------
__global__ void __launch_bounds__(NT) k_first(float* __restrict__ uout,
                                              const float* __restrict__ lam,
                                              const float* __restrict__ th) {
    int t4 = blockIdx.x * NT + threadIdx.x;
    int pix = t4 * 4;
    float tl = __ldg(th) * __ldg(lam);

    float4 GI0 = ldg4(g_gi0 + pix);
    float4 GI1 = ldg4(g_gi1 + pix);
    float4 RC  = ldg4(g_rhoc + pix);
    const float* gi0 = &GI0.x; const float* gi1 = &GI1.x; const float* rc = &RC.x;

    float o0[4], o1[4];
    #pragma unroll
    for (int i = 0; i < 4; i++) {
        float nrm = gi0[i]*gi0[i] + gi1[i]*gi1[i];
        float rho = rc[i];
        float a = fabsf(rho);
        float thv = tl * nrm;
        float a0 = 0.f, a1 = 0.f;
        if (a < thv) {
            float q = rho / nrm;
            a0 = -q * gi0[i]; a1 = -q * gi1[i];
        } else if (a > thv) {
            float s = (rho > 0.f) ? 1.f : ((rho < 0.f) ? -1.f : 0.f);
            float c = tl * s;
            a0 = -c * gi0[i]; a1 = -c * gi1[i];
        }
        o0[i] = a0; o1[i] = a1;
    }
    *(float4*)(uout + pix)      = make_float4(o0[0],o0[1],o0[2],o0[3]);
    *(float4*)(uout + HW + pix) = make_float4(o1[0],o1[1],o1[2],o1[3]);
}

// ---------------- K_R: S = sum |sobel(u)| (deterministic) ----------------
__global__ void __launch_bounds__(NT) k_reduce(const float* __restrict__ u, const float* __restrict__ gw) {
    float w0[9], w1[9];
    #pragma unroll
    for (int i = 0; i < 9; i++) { w0[i] = __ldg(&gw[i]); w1[i] = __ldg(&gw[9 + i]); }

    int t4 = blockIdx.x * NT + threadIdx.x;
    int pix = t4 * 4;
    int y = pix >> 10, x0 = pix & (WW - 1);

    float acc = 0.f;
    #pragma unroll
    for (int comp = 0; comp < 2; comp++) {
        const float* __restrict__ up = u + comp * HW;
        float t[3][6];
        #pragma unroll
        for (int r = 0; r < 3; r++) {
            int yy = y - 1 + r; bool vy = (yy >= 0 && yy < HH);
            const float* row = up + yy * WW;
            float l = (vy && x0 > 0) ? row[x0 - 1] : 0.f;
            float4 b = vy ? ldg4(row + x0) : make_float4(0.f,0.f,0.f,0.f);
            float rg = (vy && x0 < WW - 4) ? row[x0 + 4] : 0.f;
            t[r][0]=l; t[r][1]=b.x; t[r][2]=b.y; t[r][3]=b.z; t[r][4]=b.w; t[r][5]=rg;
        }
        #pragma unroll
        for (int i = 0; i < 4; i++) {
            float a = 0.f, b = 0.f;
            #pragma unroll
            for (int r = 0; r < 3; r++)
                #pragma unroll
                for (int c = 0; c < 3; c++) { float v = t[r][i + c]; a += v * w0[r*3+c]; b += v * w1[r*3+c]; }
            acc += fabsf(a) + fabsf(b);
        }
    }

    __shared__ float sm[NT];
    int tid = threadIdx.x;
    sm[tid] = acc;
    __syncthreads();
    for (int s = NT / 2; s > 0; s >>= 1) {
        if (tid < s) sm[tid] += sm[tid + s];
        __syncthreads();
    }
    __shared__ bool isLast;
    if (tid == 0) {
        g_partial[blockIdx.x] = sm[0];
        __threadfence();
        unsigned prev = atomicAdd(&g_count, 1u);
        isLast = (prev == gridDim.x - 1);
    }
    __syncthreads();
    if (isLast && tid < 32) {
        float s = 0.f;
        for (int i = tid; i < (int)gridDim.x; i += 32) s += g_partial[i];
        #pragma unroll
        for (int o = 16; o > 0; o >>= 1) s += __shfl_down_sync(0xffffffffu, s, o);
        if (tid == 0) { g_S = s; g_count = 0u; }
    }
}

// ---------------- K_F: smem-tiled fused p-recompute + u update ----------------
// Block (64,4), tile 256 cols x 4 rows, 4 strided px/thread (cols tx, tx+64, tx+128, tx+192).
// MODE 1: writes p. MODE 2: last iteration (no p write).
#define SW 264
template<int MODE>
__global__ void __launch_bounds__(NT, 5) k_fused(const float* __restrict__ uin, float* __restrict__ uout,
                        const float* __restrict__ pin, float* __restrict__ pout,
                        const float* __restrict__ gw,
                        const float* __restrict__ wx, const float* __restrict__ wy,
                        const float* __restrict__ lam, const float* __restrict__ tau,
                        const float* __restrict__ th) {
    __shared__ float su0[6][SW];          // u0 rows by0-1..by0+4, cols bx0-2..bx0+257
    __shared__ float su1[7][SW];          // u1 rows by0-2..by0+4, cols bx0-1..bx0+256
    __shared__ float sp0[4][SW], sp1[4][SW];  // np0/np1, col index c_local+1 (left halo at 0)
    __shared__ float sp2[5][SW], sp3[5][SW];  // np2/np3, row index r_local+1 (up halo at 0)
    __shared__ float sw0[9], sw1[9];

    const int tx = threadIdx.x;           // 0..63
    const int ty = threadIdx.y;           // 0..3
    const int tid = ty * 64 + tx;
    const int bx0 = blockIdx.x * 256;
    const int by0 = blockIdx.y * 4;
    const int gy  = by0 + ty;

    if (tid < 9)       sw0[tid] = gw[tid];
    else if (tid < 18) sw1[tid - 9] = gw[tid];

    const float* __restrict__ uin1 = uin + HW;
    // stage u0 halo tile: 6 x 260
    for (int i = tid; i < 6 * 260; i += NT) {
        int r = i / 260, cc = i % 260;
        int yy = by0 - 1 + r, xc = bx0 - 2 + cc;
        su0[r][cc] = (yy >= 0 && yy < HH && xc >= 0 && xc < WW) ? uin[yy * WW + xc] : 0.f;
    }
    // stage u1 halo tile: 7 x 258
    for (int i = tid; i < 7 * 258; i += NT) {
        int r = i / 258, cc = i % 258;
        int yy = by0 - 2 + r, xc = bx0 - 1 + cc;
        su1[r][cc] = (yy >= 0 && yy < HH && xc >= 0 && xc < WW) ? uin1[yy * WW + xc] : 0.f;
    }
    __syncthreads();

    const float theta = __ldg(th);
    const float tl = theta * __ldg(lam);
    const float rr = __ldg(tau) / theta;
    const float inv = 1.f / (1.f + rr * g_S);

    float v0[4], v1[4];
    #pragma unroll
    for (int j = 0; j < 4; j++) {
        int cl = tx + 64 * j;
        int pix = gy * WW + bx0 + cl;

        float s00 = 0.f, s01 = 0.f, s10 = 0.f, s11 = 0.f;
        #pragma unroll
        for (int r = 0; r < 3; r++)
            #pragma unroll
            for (int c = 0; c < 3; c++) {
                float wa = sw0[r*3+c], wb = sw1[r*3+c];
                float a = su0[ty + r][cl + 1 + c];
                float b = su1[ty + 1 + r][cl + c];
                s00 += a * wa; s01 += a * wb;
                s10 += b * wa; s11 += b * wb;
            }
        float np0 = (pin[pix]          + rr * s00) * inv;
        float np1 = (pin[HW + pix]     + rr * s01) * inv;
        float np2 = (pin[2*HW + pix]   + rr * s10) * inv;
        float np3 = (pin[3*HW + pix]   + rr * s11) * inv;
        sp0[ty][cl + 1] = np0;
        sp1[ty][cl + 1] = np1;
        sp2[ty + 1][cl] = np2;
        sp3[ty + 1][cl] = np3;
        if (MODE == 1) {
            pout[pix]          = np0;
            pout[HW + pix]     = np1;
            pout[2*HW + pix]   = np2;
            pout[3*HW + pix]   = np3;
        }

        float u0c = su0[ty + 1][cl + 2];
        float u1c = su1[ty + 2][cl + 1];
        float gi0 = g_gi0[pix], gi1 = g_gi1[pix];
        float nrm = gi0 * gi0 + gi1 * gi1;
        float rho = g_rhoc[pix] + gi0 * u0c + gi1 * u1c;
        float a = fabsf(rho);
        float thv = tl * nrm;
        float a0 = u0c, a1 = u1c;
        if (a < thv) {
            float q = rho / nrm;
            a0 -= q * gi0; a1 -= q * gi1;
        } else if (a > thv) {
            float s = (rho > 0.f) ? 1.f : ((rho < 0.f) ? -1.f : 0.f);
            float c = tl * s;
            a0 -= c * gi0; a1 -= c * gi1;
        }
        v0[j] = a0; v1[j] = a1;
    }

    // left halo np at col bx0-1 (rows gy)
    if (tx == 0) {
        float h0 = 0.f, h1 = 0.f;
        if (bx0 > 0) {
            float s0 = 0.f, s1 = 0.f;
            #pragma unroll
            for (int r = 0; r < 3; r++)
                #pragma unroll
                for (int c = 0; c < 3; c++) {
                    float a = su0[ty + r][c];
                    s0 += a * sw0[r*3+c]; s1 += a * sw1[r*3+c];
                }
            int pixh = gy * WW + bx0 - 1;
            h0 = (pin[pixh]      + rr * s0) * inv;
            h1 = (pin[HW + pixh] + rr * s1) * inv;
        }
        sp0[ty][0] = h0;
        sp1[ty][0] = h1;
    }
    // up halo np at row by0-1 (4 chunks)
    if (ty == 0) {
        #pragma unroll
        for (int j = 0; j < 4; j++) {
            int cl = tx + 64 * j;
            float h2 = 0.f, h3 = 0.f;
            if (by0 > 0) {
                float s2 = 0.f, s3 = 0.f;
                #pragma unroll
                for (int r = 0; r < 3; r++)
                    #pragma unroll
                    for (int c = 0; c < 3; c++) {
                        float b = su1[r][cl + c];
                        s2 += b * sw0[r*3+c]; s3 += b * sw1[r*3+c];
                    }
                int pixh = (by0 - 1) * WW + bx0 + cl;
                h2 = (pin[2*HW + pixh] + rr * s2) * inv;
                h3 = (pin[3*HW + pixh] + rr * s3) * inv;
            }
            sp2[0][cl] = h2;
            sp3[0][cl] = h3;
        }
    }
    __syncthreads();

    const float wx0 = __ldg(&wx[0]), wx1v = __ldg(&wx[1]);
    const float wy0 = __ldg(&wy[0]), wy1v = __ldg(&wy[1]);

    #pragma unroll
    for (int j = 0; j < 4; j++) {
        int cl = tx + 64 * j;
        int pix = gy * WW + bx0 + cl;
        float np0 = sp0[ty][cl + 1], np1 = sp1[ty][cl + 1];
        float np2 = sp2[ty + 1][cl], np3 = sp3[ty + 1][cl];
        float pL0 = sp0[ty][cl],     pL1 = sp1[ty][cl];
        float pU2 = sp2[ty][cl],     pU3 = sp3[ty][cl];
        float d0 = pL0 * wx0 + np0 * wx1v + pU2 * wy0 + np2 * wy1v;
        float d1 = pL1 * wx0 + np1 * wx1v + pU3 * wy0 + np3 * wy1v;
        uout[pix]      = v0[j] + theta * d0;
        uout[HW + pix] = v1[j] + theta * d1;
    }
}

// ---------------- launch ----------------
extern "C" void kernel_launch(void* const* d_in, const int* in_sizes, int n_in,
                              void* d_out, int out_size) {
    const float* x   = (const float*)d_in[0];
    const float* gw  = (const float*)d_in[1];
    const float* wx  = (const float*)d_in[2];
    const float* wy  = (const float*)d_in[3];
    const float* lam = (const float*)d_in[4];
    const float* tau = (const float*)d_in[5];
    const float* th  = (const float*)d_in[6];
    float* out = (float*)d_out;

    float* ubase; cudaGetSymbolAddress((void**)&ubase, g_u);
    float* pbase; cudaGetSymbolAddress((void**)&pbase, g_p);
    float* ubuf[2] = { ubase, ubase + 2*HW };
    float* pbuf[2] = { pbase, pbase + 4*HW };

    dim3 fblk(64, 4);
    dim3 fgrd(WW / 256, HH / 4);   // (4, 256)

    k_init<<<NB4, NT>>>(x, gw);
    k_first<<<NB4, NT>>>(ubuf[1], lam, th);

    for (int t = 1; t <= 9; t++) {
        k_reduce<<<NB4, NT>>>(ubuf[t & 1], gw);
        float* uo = (t == 9) ? out : ubuf[(t + 1) & 1];
        if (t < 9)
            k_fused<1><<<fgrd, fblk>>>(ubuf[t & 1], uo, pbuf[(t + 1) & 1], pbuf[t & 1],
                                       gw, wx, wy, lam, tau, th);
        else
            k_fused<2><<<fgrd, fblk>>>(ubuf[t & 1], uo, pbuf[(t + 1) & 1], nullptr,
                                       gw, wx, wy, lam, tau, th);
    }
}

// round 5
// speedup vs baseline: 1.5525x; 1.5525x over previous
#include <cuda_runtime.h>

#define HH 1024
#define WW 1024
#define HW (HH*WW)
#define NT 256
#define NB4 (HW/4/NT)   // 1024 blocks, 4 px/thread

// ---------------- constants (filled via capture-legal D2D memcpy) ----------------
__constant__ float c_gw[18];
__constant__ float c_wx[2];
__constant__ float c_wy[2];
__constant__ float c_lam;
__constant__ float c_tau;
__constant__ float c_th;

// ---------------- device scratch ----------------
__device__ __align__(16) float g_rhoc[HW];
__device__ __align__(16) float g_gi0[HW];
__device__ __align__(16) float g_gi1[HW];
__device__ __align__(16) float g_u[2][2*HW];
__device__ __align__(16) float g_p[2][4*HW];
__device__ float g_partial[NB4];
__device__ unsigned int g_count;
__device__ float g_S;

__device__ __forceinline__ float4 ldg4(const float* p) { return *(const float4*)p; }
__device__ __forceinline__ float2 ldg2(const float* p) { return *(const float2*)p; }

// ---------------- K0: rho_c, grad_im; zero P_0 ----------------
__global__ void __launch_bounds__(NT) k_init(const float* __restrict__ x) {
    int t4 = blockIdx.x * NT + threadIdx.x;
    int pix = t4 * 4;
    int y = pix >> 10, x0 = pix & (WW - 1);
    const float* __restrict__ x1 = x + HW;

    float t[3][6];
    #pragma unroll
    for (int r = 0; r < 3; r++) {
        int yy = y - 1 + r; bool vy = (yy >= 0 && yy < HH);
        const float* row = x1 + yy * WW;
        float l = (vy && x0 > 0) ? row[x0 - 1] : 0.f;
        float4 b = vy ? ldg4(row + x0) : make_float4(0.f,0.f,0.f,0.f);
        float rg = (vy && x0 < WW - 4) ? row[x0 + 4] : 0.f;
        t[r][0]=l; t[r][1]=b.x; t[r][2]=b.y; t[r][3]=b.z; t[r][4]=b.w; t[r][5]=rg;
    }

    float4 xc0 = ldg4(x + pix);
    float4 xc1 = ldg4(x1 + pix);
    *(float4*)(g_rhoc + pix) = make_float4(xc1.x-xc0.x, xc1.y-xc0.y, xc1.z-xc0.z, xc1.w-xc0.w);

    float4 A, B;
    float* Ap = &A.x; float* Bp = &B.x;
    #pragma unroll
    for (int i = 0; i < 4; i++) {
        float a = 0.f, b = 0.f;
        #pragma unroll
        for (int r = 0; r < 3; r++)
            #pragma unroll
            for (int c = 0; c < 3; c++) { float v = t[r][i + c]; a += v * c_gw[r*3+c]; b += v * c_gw[9 + r*3+c]; }
        Ap[i] = a; Bp[i] = b;
    }
    *(float4*)(g_gi0 + pix) = A;
    *(float4*)(g_gi1 + pix) = B;

    float4 z = make_float4(0.f,0.f,0.f,0.f);
    *(float4*)(g_p[0] + pix) = z;
    *(float4*)(g_p[0] + HW + pix) = z;
    *(float4*)(g_p[0] + 2*HW + pix) = z;
    *(float4*)(g_p[0] + 3*HW + pix) = z;
    if (pix == 0) g_count = 0u;
}

// ---------------- K_first: t=0 (u=0, p=0) ----------------
__global__ void __launch_bounds__(NT) k_first(float* __restrict__ uout) {
    int t4 = blockIdx.x * NT + threadIdx.x;
    int pix = t4 * 4;
    float tl = c_th * c_lam;

    float4 GI0 = ldg4(g_gi0 + pix);
    float4 GI1 = ldg4(g_gi1 + pix);
    float4 RC  = ldg4(g_rhoc + pix);
    const float* gi0 = &GI0.x; const float* gi1 = &GI1.x; const float* rc = &RC.x;

    float o0[4], o1[4];
    #pragma unroll
    for (int i = 0; i < 4; i++) {
        float nrm = gi0[i]*gi0[i] + gi1[i]*gi1[i];
        float rho = rc[i];
        float a = fabsf(rho);
        float thv = tl * nrm;
        float a0 = 0.f, a1 = 0.f;
        if (a < thv) {
            float q = rho / nrm;
            a0 = -q * gi0[i]; a1 = -q * gi1[i];
        } else if (a > thv) {
            float s = (rho > 0.f) ? 1.f : ((rho < 0.f) ? -1.f : 0.f);
            float c = tl * s;
            a0 = -c * gi0[i]; a1 = -c * gi1[i];
        }
        o0[i] = a0; o1[i] = a1;
    }
    *(float4*)(uout + pix)      = make_float4(o0[0],o0[1],o0[2],o0[3]);
    *(float4*)(uout + HW + pix) = make_float4(o1[0],o1[1],o1[2],o1[3]);
}

// ---------------- K_R: S = sum |sobel(u)| (deterministic) ----------------
__global__ void __launch_bounds__(NT) k_reduce(const float* __restrict__ u) {
    int t4 = blockIdx.x * NT + threadIdx.x;
    int pix = t4 * 4;
    int y = pix >> 10, x0 = pix & (WW - 1);

    float acc = 0.f;
    #pragma unroll
    for (int comp = 0; comp < 2; comp++) {
        const float* __restrict__ up = u + comp * HW;
        float t[3][6];
        #pragma unroll
        for (int r = 0; r < 3; r++) {
            int yy = y - 1 + r; bool vy = (yy >= 0 && yy < HH);
            const float* row = up + yy * WW;
            float l = (vy && x0 > 0) ? row[x0 - 1] : 0.f;
            float4 b = vy ? ldg4(row + x0) : make_float4(0.f,0.f,0.f,0.f);
            float rg = (vy && x0 < WW - 4) ? row[x0 + 4] : 0.f;
            t[r][0]=l; t[r][1]=b.x; t[r][2]=b.y; t[r][3]=b.z; t[r][4]=b.w; t[r][5]=rg;
        }
        #pragma unroll
        for (int i = 0; i < 4; i++) {
            float a = 0.f, b = 0.f;
            #pragma unroll
            for (int r = 0; r < 3; r++)
                #pragma unroll
                for (int c = 0; c < 3; c++) { float v = t[r][i + c]; a += v * c_gw[r*3+c]; b += v * c_gw[9 + r*3+c]; }
            acc += fabsf(a) + fabsf(b);
        }
    }

    __shared__ float sm[NT];
    int tid = threadIdx.x;
    sm[tid] = acc;
    __syncthreads();
    for (int s = NT / 2; s > 0; s >>= 1) {
        if (tid < s) sm[tid] += sm[tid + s];
        __syncthreads();
    }
    __shared__ bool isLast;
    if (tid == 0) {
        g_partial[blockIdx.x] = sm[0];
        __threadfence();
        unsigned prev = atomicAdd(&g_count, 1u);
        isLast = (prev == gridDim.x - 1);
    }
    __syncthreads();
    if (isLast && tid < 32) {
        float s = 0.f;
        for (int i = tid; i < (int)gridDim.x; i += 32) s += g_partial[i];
        #pragma unroll
        for (int o = 16; o > 0; o >>= 1) s += __shfl_down_sync(0xffffffffu, s, o);
        if (tid == 0) { g_S = s; g_count = 0u; }
    }
}

// ---------------- K_F: fused p-recompute + u update, 4 px/thread, row-streaming ----------------
// MODE 1: mid (writes p). MODE 2: last (no p write).
template<int MODE>
__global__ void __launch_bounds__(NT, 4) k_fused(const float* __restrict__ uin, float* __restrict__ uout,
                        const float* __restrict__ pin, float* __restrict__ pout) {
    int t4 = blockIdx.x * NT + threadIdx.x;
    int pix = t4 * 4;
    int y = pix >> 10, x0 = pix & (WW - 1);

    const float theta = c_th;
    const float tl = theta * c_lam;
    const float rr = c_tau / theta;
    const float inv = 1.f / (1.f + rr * g_S);

    // ---- u0 component: sobels at own[0..3] and left; centers ----
    float G00[4] = {0.f,0.f,0.f,0.f}, G01[4] = {0.f,0.f,0.f,0.f};
    float L00 = 0.f, L01 = 0.f;
    float u0c[4];
    #pragma unroll
    for (int r = 0; r < 3; r++) {
        int yy = y - 1 + r; bool vy = (yy >= 0 && yy < HH);
        const float* row = uin + yy * WW;
        float2 a = (vy && x0 > 0) ? ldg2(row + x0 - 2) : make_float2(0.f,0.f);
        float4 b = vy ? ldg4(row + x0) : make_float4(0.f,0.f,0.f,0.f);
        float2 c = (vy && x0 < WW - 4) ? ldg2(row + x0 + 4) : make_float2(0.f,0.f);
        float rw[8] = {a.x, a.y, b.x, b.y, b.z, b.w, c.x, c.y};
        if (r == 1) { u0c[0]=rw[2]; u0c[1]=rw[3]; u0c[2]=rw[4]; u0c[3]=rw[5]; }
        #pragma unroll
        for (int cc = 0; cc < 3; cc++) {
            float wa = c_gw[r*3+cc], wb = c_gw[9 + r*3+cc];
            L00 += rw[cc] * wa; L01 += rw[cc] * wb;
            #pragma unroll
            for (int i = 0; i < 4; i++) {
                G00[i] += rw[i + 1 + cc] * wa;
                G01[i] += rw[i + 1 + cc] * wb;
            }
        }
    }

    // ---- u1 component: sobels at own[0..3] and up; centers ----
    float G10[4] = {0.f,0.f,0.f,0.f}, G11[4] = {0.f,0.f,0.f,0.f};
    float U10[4] = {0.f,0.f,0.f,0.f}, U11[4] = {0.f,0.f,0.f,0.f};
    float u1c[4];
    const float* __restrict__ uin1 = uin + HW;
    #pragma unroll
    for (int r = 0; r < 4; r++) {
        int yy = y - 2 + r; bool vy = (yy >= 0 && yy < HH);
        const float* row = uin1 + yy * WW;
        float l = (vy && x0 > 0) ? row[x0 - 1] : 0.f;
        float4 b = vy ? ldg4(row + x0) : make_float4(0.f,0.f,0.f,0.f);
        float rg = (vy && x0 < WW - 4) ? row[x0 + 4] : 0.f;
        float rw[6] = {l, b.x, b.y, b.z, b.w, rg};
        if (r == 2) { u1c[0]=rw[1]; u1c[1]=rw[2]; u1c[2]=rw[3]; u1c[3]=rw[4]; }
        if (r < 3) {
            #pragma unroll
            for (int cc = 0; cc < 3; cc++) {
                float wa = c_gw[r*3+cc], wb = c_gw[9 + r*3+cc];
                #pragma unroll
                for (int i = 0; i < 4; i++) {
                    U10[i] += rw[i + cc] * wa;
                    U11[i] += rw[i + cc] * wb;
                }
            }
        }
        if (r > 0) {
            int rk = r - 1;
            #pragma unroll
            for (int cc = 0; cc < 3; cc++) {
                float wa = c_gw[rk*3+cc], wb = c_gw[9 + rk*3+cc];
                #pragma unroll
                for (int i = 0; i < 4; i++) {
                    G10[i] += rw[i + cc] * wa;
                    G11[i] += rw[i + cc] * wb;
                }
            }
        }
    }

    // ---- pointwise v update ----
    float4 GI0 = ldg4(g_gi0 + pix);
    float4 GI1 = ldg4(g_gi1 + pix);
    float4 RC  = ldg4(g_rhoc + pix);
    const float* gi0 = &GI0.x; const float* gi1 = &GI1.x; const float* rc = &RC.x;

    float v0[4], v1[4];
    #pragma unroll
    for (int i = 0; i < 4; i++) {
        float nrm = gi0[i]*gi0[i] + gi1[i]*gi1[i];
        float rho = rc[i] + gi0[i]*u0c[i] + gi1[i]*u1c[i];
        float a = fabsf(rho);
        float thv = tl * nrm;
        float a0 = u0c[i], a1 = u1c[i];
        if (a < thv) {
            float q = rho / nrm;
            a0 -= q * gi0[i]; a1 -= q * gi1[i];
        } else if (a > thv) {
            float s = (rho > 0.f) ? 1.f : ((rho < 0.f) ? -1.f : 0.f);
            float c = tl * s;
            a0 -= c * gi0[i]; a1 -= c * gi1[i];
        }
        v0[i] = a0; v1[i] = a1;
    }

    // ---- p recompute at own / left / up ----
    float4 P0 = ldg4(pin + pix);
    float4 P1 = ldg4(pin + HW + pix);
    float4 P2 = ldg4(pin + 2*HW + pix);
    float4 P3 = ldg4(pin + 3*HW + pix);
    const float* p0 = &P0.x; const float* p1 = &P1.x;
    const float* p2 = &P2.x; const float* p3 = &P3.x;

    bool hasU = (y > 0);
    float4 PU2 = hasU ? ldg4(pin + 2*HW + pix - WW) : make_float4(0.f,0.f,0.f,0.f);
    float4 PU3 = hasU ? ldg4(pin + 3*HW + pix - WW) : make_float4(0.f,0.f,0.f,0.f);
    const float* pu2 = &PU2.x; const float* pu3 = &PU3.x;

    bool hasL = (x0 > 0);
    float pl0 = hasL ? pin[pix - 1]      : 0.f;
    float pl1 = hasL ? pin[HW + pix - 1] : 0.f;

    float np0[4], np1[4], np2[4], np3[4];
    #pragma unroll
    for (int i = 0; i < 4; i++) {
        np0[i] = (p0[i] + rr * G00[i]) * inv;
        np1[i] = (p1[i] + rr * G01[i]) * inv;
        np2[i] = (p2[i] + rr * G10[i]) * inv;
        np3[i] = (p3[i] + rr * G11[i]) * inv;
    }
    float lft0 = hasL ? (pl0 + rr * L00) * inv : 0.f;
    float lft1 = hasL ? (pl1 + rr * L01) * inv : 0.f;

    const float wx0 = c_wx[0], wx1v = c_wx[1];
    const float wy0 = c_wy[0], wy1v = c_wy[1];

    float o0[4], o1[4];
    #pragma unroll
    for (int i = 0; i < 4; i++) {
        float pL0 = (i == 0) ? lft0 : np0[i-1];
        float pL1 = (i == 0) ? lft1 : np1[i-1];
        float pU2 = hasU ? (pu2[i] + rr * U10[i]) * inv : 0.f;
        float pU3 = hasU ? (pu3[i] + rr * U11[i]) * inv : 0.f;
        float d0 = pL0 * wx0 + np0[i] * wx1v + pU2 * wy0 + np2[i] * wy1v;
        float d1 = pL1 * wx0 + np1[i] * wx1v + pU3 * wy0 + np3[i] * wy1v;
        o0[i] = v0[i] + theta * d0;
        o1[i] = v1[i] + theta * d1;
    }

    *(float4*)(uout + pix)      = make_float4(o0[0],o0[1],o0[2],o0[3]);
    *(float4*)(uout + HW + pix) = make_float4(o1[0],o1[1],o1[2],o1[3]);

    if (MODE == 1) {
        *(float4*)(pout + pix)        = make_float4(np0[0],np0[1],np0[2],np0[3]);
        *(float4*)(pout + HW + pix)   = make_float4(np1[0],np1[1],np1[2],np1[3]);
        *(float4*)(pout + 2*HW + pix) = make_float4(np2[0],np2[1],np2[2],np2[3]);
        *(float4*)(pout + 3*HW + pix) = make_float4(np3[0],np3[1],np3[2],np3[3]);
    }
}

// ---------------- launch ----------------
extern "C" void kernel_launch(void* const* d_in, const int* in_sizes, int n_in,
                              void* d_out, int out_size) {
    const float* x   = (const float*)d_in[0];
    const float* gw  = (const float*)d_in[1];
    const float* wx  = (const float*)d_in[2];
    const float* wy  = (const float*)d_in[3];
    const float* lam = (const float*)d_in[4];
    const float* tau = (const float*)d_in[5];
    const float* th  = (const float*)d_in[6];
    float* out = (float*)d_out;

    // capture-legal D2D copies into __constant__
    cudaMemcpyToSymbolAsync(c_gw,  gw,  18*sizeof(float), 0, cudaMemcpyDeviceToDevice);
    cudaMemcpyToSymbolAsync(c_wx,  wx,   2*sizeof(float), 0, cudaMemcpyDeviceToDevice);
    cudaMemcpyToSymbolAsync(c_wy,  wy,   2*sizeof(float), 0, cudaMemcpyDeviceToDevice);
    cudaMemcpyToSymbolAsync(c_lam, lam,    sizeof(float), 0, cudaMemcpyDeviceToDevice);
    cudaMemcpyToSymbolAsync(c_tau, tau,    sizeof(float), 0, cudaMemcpyDeviceToDevice);
    cudaMemcpyToSymbolAsync(c_th,  th,     sizeof(float), 0, cudaMemcpyDeviceToDevice);

    float* ubase; cudaGetSymbolAddress((void**)&ubase, g_u);
    float* pbase; cudaGetSymbolAddress((void**)&pbase, g_p);
    float* ubuf[2] = { ubase, ubase + 2*HW };
    float* pbuf[2] = { pbase, pbase + 4*HW };

    k_init<<<NB4, NT>>>(x);
    k_first<<<NB4, NT>>>(ubuf[1]);

    for (int t = 1; t <= 9; t++) {
        k_reduce<<<NB4, NT>>>(ubuf[t & 1]);
        float* uo = (t == 9) ? out : ubuf[(t + 1) & 1];
        if (t < 9)
            k_fused<1><<<NB4, NT>>>(ubuf[t & 1], uo, pbuf[(t + 1) & 1], pbuf[t & 1]);
        else
            k_fused<2><<<NB4, NT>>>(ubuf[t & 1], uo, pbuf[(t + 1) & 1], nullptr);
    }
}